// round 8
// baseline (speedup 1.0000x reference)
#include <cuda_runtime.h>

#define NODES 50000
#define EDGES 800000
#define NTYPE 3
#define CH    64

__device__ float d_A[NTYPE * NODES * CH];
__device__ float d_B[NTYPE * NODES * CH];
__device__ float d_S[NTYPE * NODES * CH];
__device__ int   d_cnt[NTYPE * NODES];
__device__ float d_sumP[NTYPE * CH];
__device__ float d_sumQ[NTYPE * CH];
__device__ float d_scale[NTYPE * CH];
__device__ float d_shift[NTYPE * CH];
__device__ int   d_src[NTYPE * EDGES];
__device__ int   d_dst[NTYPE * EDGES];

static __device__ __forceinline__ unsigned long long pack2(float x, float y) {
    unsigned long long r;
    asm("mov.b64 %0, {%1,%2};" : "=l"(r) : "f"(x), "f"(y));
    return r;
}
static __device__ __forceinline__ float2 unpack2(unsigned long long v) {
    float2 f;
    asm("mov.b64 {%0,%1}, %2;" : "=f"(f.x), "=f"(f.y) : "l"(v));
    return f;
}
static __device__ __forceinline__ void ffma2(unsigned long long& d,
                                             unsigned long long a,
                                             unsigned long long b) {
    asm("fma.rn.f32x2 %0, %1, %2, %0;" : "+l"(d) : "l"(a), "l"(b));
}
static __device__ __forceinline__ void red2(float* addr, float x, float y) {
    asm volatile("red.global.add.v2.f32 [%0], {%1, %2};"
                 :: "l"(addr), "f"(x), "f"(y) : "memory");
}
static __device__ __forceinline__ float elu1(float x) {
    return x > 0.f ? x : (__expf(x) - 1.f);
}

// ---- K0: fused detect + index convert + scratch zero ----
__global__ void k_prep(const void* __restrict__ sraw, const void* __restrict__ draw) {
    // int64 detection: in int32 mode the odd words are random node ids; 64
    // consecutive zero high-words only happens for genuine int64 input.
    const int* r32 = (const int*)sraw;
    int is64 = 1;
#pragma unroll
    for (int m = 0; m < 64; m++)
        if (r32[2 * m + 1] != 0) { is64 = 0; break; }

    long long i = (long long)blockIdx.x * blockDim.x + threadIdx.x;
    if (i < (long long)NTYPE * EDGES) {
        if (is64) {
            d_src[i] = (int)((const long long*)sraw)[i];
            d_dst[i] = (int)((const long long*)draw)[i];
        } else {
            d_src[i] = ((const int*)sraw)[i];
            d_dst[i] = ((const int*)draw)[i];
        }
    }
    if (i < (long long)NTYPE * NODES * CH / 4)
        ((float4*)d_S)[i] = make_float4(0.f, 0.f, 0.f, 0.f);
    if (i < NTYPE * NODES) d_cnt[i] = 0;
    if (i < NTYPE * CH) { d_sumP[i] = 0.f; d_sumQ[i] = 0.f; }
}

// ---- K1: precompute A/B = features @ W1 halves ----
__global__ void __launch_bounds__(128) k_pre(const float* __restrict__ feats,
                                             const float* __restrict__ W1) {
    __shared__ float w1t[128 * 64];
    const int t = blockIdx.y;
    const float* W1t = W1 + t * 128 * 64;
    for (int i = threadIdx.x; i < 128 * 64; i += 128) {
        int o = i >> 6, k = i & 63;
        w1t[i] = W1t[(((o >> 6) << 6) + k) * 64 + (o & 63)];
    }
    __syncthreads();
    int n = blockIdx.x * 128 + threadIdx.x;
    if (n >= NODES) return;

    float f[64];
#pragma unroll
    for (int j = 0; j < 16; j++) {
        float4 v = *(const float4*)(feats + (size_t)n * 64 + 4 * j);
        f[4 * j] = v.x; f[4 * j + 1] = v.y; f[4 * j + 2] = v.z; f[4 * j + 3] = v.w;
    }
    float* outA = d_A + ((size_t)t * NODES + n) * 64;
    float* outB = d_B + ((size_t)t * NODES + n) * 64;

    for (int og = 0; og < 32; og++) {
        float a0 = 0.f, a1 = 0.f, a2 = 0.f, a3 = 0.f;
        const float* wp = &w1t[og * 4 * 64];
#pragma unroll
        for (int k = 0; k < 64; k += 4) {
            float4 v0 = *(const float4*)(wp + 0 * 64 + k);
            float4 v1 = *(const float4*)(wp + 1 * 64 + k);
            float4 v2 = *(const float4*)(wp + 2 * 64 + k);
            float4 v3 = *(const float4*)(wp + 3 * 64 + k);
            a0 = fmaf(v0.x, f[k], a0); a0 = fmaf(v0.y, f[k + 1], a0);
            a0 = fmaf(v0.z, f[k + 2], a0); a0 = fmaf(v0.w, f[k + 3], a0);
            a1 = fmaf(v1.x, f[k], a1); a1 = fmaf(v1.y, f[k + 1], a1);
            a1 = fmaf(v1.z, f[k + 2], a1); a1 = fmaf(v1.w, f[k + 3], a1);
            a2 = fmaf(v2.x, f[k], a2); a2 = fmaf(v2.y, f[k + 1], a2);
            a2 = fmaf(v2.z, f[k + 2], a2); a2 = fmaf(v2.w, f[k + 3], a2);
            a3 = fmaf(v3.x, f[k], a3); a3 = fmaf(v3.y, f[k + 1], a3);
            a3 = fmaf(v3.z, f[k + 2], a3); a3 = fmaf(v3.w, f[k + 3], a3);
        }
        float4 r = make_float4(a0, a1, a2, a3);
        if (og < 16) *(float4*)(outA + og * 4) = r;
        else         *(float4*)(outB + (og - 16) * 4) = r;
    }
}

// ---- K2: edge kernel — LN folded into GEMM epilogue (shuffles off critical path) ----
__global__ void __launch_bounds__(128, 2) k_edge(const float* __restrict__ W2,
                                                 const float* __restrict__ b1,
                                                 const float* __restrict__ lng,
                                                 const float* __restrict__ lnb,
                                                 const float* __restrict__ b2,
                                                 int qlo, int qhi) {
    const int t = blockIdx.y;
    const int w = threadIdx.x >> 5;
    const int lane = threadIdx.x & 31;
    const int c0 = lane * 2;

    __shared__ __align__(16) float hdup[4][4][128];

    // w2r[k] = g[k]*W2[t][k][c0..c0+1];  K = sum_k w2r[k];  L = beta@W2 + b2
    unsigned long long w2r[64];
    float2 Kp = make_float2(0.f, 0.f);
    float2 Lp = *(const float2*)(b2 + t * 64 + c0);
    {
        const float* W2t = W2 + t * 64 * 64 + c0;
#pragma unroll
        for (int k = 0; k < 64; k++) {
            float2 wv = *(const float2*)(W2t + k * 64);
            const float gk = lng[t * 64 + k];
            const float bk = lnb[t * 64 + k];
            Lp.x = fmaf(bk, wv.x, Lp.x);
            Lp.y = fmaf(bk, wv.y, Lp.y);
            const float wgx = gk * wv.x, wgy = gk * wv.y;
            Kp.x += wgx; Kp.y += wgy;
            w2r[k] = pack2(wgx, wgy);
        }
    }
    const float2 b1v = *(const float2*)(b1 + t * 64 + c0);

    const int*   srcp = d_src + (size_t)t * EDGES;
    const int*   dstp = d_dst + (size_t)t * EDGES;
    const float* At   = d_A + (size_t)t * NODES * 64;
    const float* Bt   = d_B + (size_t)t * NODES * 64;
    float*       St   = d_S + (size_t)t * NODES * 64;
    int*         cntp = d_cnt + (size_t)t * NODES;

    float sp0 = 0.f, sp1 = 0.f, sq0 = 0.f, sq1 = 0.f;
    const int qstride = gridDim.x * 4;

    for (int q = qlo + blockIdx.x * 4 + w; q < qhi; q += qstride) {
        const int e = q * 4;
        int dst[4];
        float h0[4], h1[4], s[4], qq[4];
#pragma unroll
        for (int i = 0; i < 4; i++) {
            const int sidx = srcp[e + i];
            dst[i] = dstp[e + i];
            float2 av = *(const float2*)(At + (size_t)sidx * 64 + c0);
            float2 bv = *(const float2*)(Bt + (size_t)dst[i] * 64 + c0);
            h0[i] = elu1(av.x + bv.x + b1v.x);
            h1[i] = elu1(av.y + bv.y + b1v.y);
            // raw h to shared immediately — GEMM input does not wait on LN
            *(float4*)(&hdup[w][i][4 * lane]) = make_float4(h0[i], h0[i], h1[i], h1[i]);
            s[i]  = h0[i] + h1[i];
            qq[i] = fmaf(h0[i], h0[i], h1[i] * h1[i]);
        }
        __syncwarp();

        // shuffle reductions (MIO pipe) overlap the GEMM below (FMA pipe)
#pragma unroll
        for (int off = 16; off; off >>= 1) {
#pragma unroll
            for (int i = 0; i < 4; i++) {
                s[i]  += __shfl_xor_sync(0xffffffffu, s[i], off);
                qq[i] += __shfl_xor_sync(0xffffffffu, qq[i], off);
            }
        }

        unsigned long long accA[4], accB[4];
#pragma unroll
        for (int i = 0; i < 4; i++) { accA[i] = 0ULL; accB[i] = 0ULL; }
        const ulonglong2* hp0 = (const ulonglong2*)&hdup[w][0][0];
        const ulonglong2* hp1 = (const ulonglong2*)&hdup[w][1][0];
        const ulonglong2* hp2 = (const ulonglong2*)&hdup[w][2][0];
        const ulonglong2* hp3 = (const ulonglong2*)&hdup[w][3][0];
#pragma unroll
        for (int kk = 0; kk < 32; kk++) {
            const unsigned long long wA = w2r[2 * kk];
            const unsigned long long wB = w2r[2 * kk + 1];
            ulonglong2 g0 = hp0[kk];
            ulonglong2 g1 = hp1[kk];
            ulonglong2 g2 = hp2[kk];
            ulonglong2 g3 = hp3[kk];
            ffma2(accA[0], g0.x, wA); ffma2(accB[0], g0.y, wB);
            ffma2(accA[1], g1.x, wA); ffma2(accB[1], g1.y, wB);
            ffma2(accA[2], g2.x, wA); ffma2(accB[2], g2.y, wB);
            ffma2(accA[3], g3.x, wA); ffma2(accB[3], g3.y, wB);
        }

        float p0[4], p1[4];
#pragma unroll
        for (int i = 0; i < 4; i++) {
            const float mu = s[i] * (1.f / 64.f);
            const float rs = rsqrtf(fmaf(qq[i], (1.f / 64.f), -mu * mu) + 1e-5f);
            const float rm = -rs * mu;
            float2 ra = unpack2(accA[i]);
            float2 rb = unpack2(accB[i]);
            // p = rs*G + rm*K + L
            p0[i] = elu1(fmaf(rs, ra.x + rb.x, fmaf(rm, Kp.x, Lp.x)));
            p1[i] = elu1(fmaf(rs, ra.y + rb.y, fmaf(rm, Kp.y, Lp.y)));
            sp0 += p0[i];
            sp1 += p1[i];
            sq0 = fmaf(p0[i], p0[i], sq0);
            sq1 = fmaf(p1[i], p1[i], sq1);
        }

        red2(St + (size_t)dst[0] * 64 + c0, p0[0], p1[0]);
        red2(St + (size_t)dst[1] * 64 + c0, p0[1], p1[1]);
        red2(St + (size_t)dst[2] * 64 + c0, p0[2], p1[2]);
        red2(St + (size_t)dst[3] * 64 + c0, p0[3], p1[3]);
        {
            int mydst = dst[0];
            if (lane == 1) mydst = dst[1];
            else if (lane == 2) mydst = dst[2];
            else if (lane == 3) mydst = dst[3];
            if (lane < 4) atomicAdd(cntp + mydst, 1);
        }
        __syncwarp();
    }
    atomicAdd(d_sumP + t * 64 + c0,     sp0);
    atomicAdd(d_sumP + t * 64 + c0 + 1, sp1);
    atomicAdd(d_sumQ + t * 64 + c0,     sq0);
    atomicAdd(d_sumQ + t * 64 + c0 + 1, sq1);
}

__global__ void k_stats(const float* __restrict__ bng, const float* __restrict__ bnb) {
    int i = threadIdx.x;
    if (i < NTYPE * CH) {
        const float invE = 1.f / (float)EDGES;
        float m = d_sumP[i] * invE;
        float v = fmaf(d_sumQ[i], invE, -m * m);
        float sc = bng[i] * rsqrtf(v + 1e-5f);
        d_scale[i] = sc;
        d_shift[i] = fmaf(-m, sc, bnb[i]);
    }
}

__global__ void __launch_bounds__(128) k_node(const float* __restrict__ feats,
                                              const float* __restrict__ Wr,
                                              const float* __restrict__ br,
                                              float* __restrict__ out) {
    __shared__ float wr[64 * 64];
    __shared__ float sc[NTYPE * CH], sh[NTYPE * CH];
    for (int i = threadIdx.x; i < 64 * 64; i += 128) wr[i] = Wr[i];
    for (int i = threadIdx.x; i < NTYPE * CH; i += 128) {
        sc[i] = d_scale[i];
        sh[i] = d_shift[i];
    }
    __syncthreads();

    int n = blockIdx.x * 128 + threadIdx.x;
    if (n >= NODES) return;

    float u[64];
#pragma unroll
    for (int c = 0; c < 64; c++) u[c] = 0.f;
#pragma unroll
    for (int t = 0; t < NTYPE; t++) {
        const float cf = (float)d_cnt[t * NODES + n];
        const float* Sn = d_S + ((size_t)t * NODES + n) * 64;
#pragma unroll
        for (int j = 0; j < 16; j++) {
            float4 sv = *(const float4*)(Sn + 4 * j);
            u[4 * j + 0] = fmaf(sc[t * 64 + 4 * j + 0], sv.x, fmaf(sh[t * 64 + 4 * j + 0], cf, u[4 * j + 0]));
            u[4 * j + 1] = fmaf(sc[t * 64 + 4 * j + 1], sv.y, fmaf(sh[t * 64 + 4 * j + 1], cf, u[4 * j + 1]));
            u[4 * j + 2] = fmaf(sc[t * 64 + 4 * j + 2], sv.z, fmaf(sh[t * 64 + 4 * j + 2], cf, u[4 * j + 2]));
            u[4 * j + 3] = fmaf(sc[t * 64 + 4 * j + 3], sv.w, fmaf(sh[t * 64 + 4 * j + 3], cf, u[4 * j + 3]));
        }
    }

    const float* fn = feats + (size_t)n * 64;
    float* on = out + (size_t)n * 64;
    for (int o = 0; o < 64; o += 4) {
        float a0 = br[o], a1 = br[o + 1], a2 = br[o + 2], a3 = br[o + 3];
#pragma unroll
        for (int k = 0; k < 64; k++) {
            float4 wv = *(const float4*)(&wr[k * 64 + o]);
            a0 = fmaf(u[k], wv.x, a0);
            a1 = fmaf(u[k], wv.y, a1);
            a2 = fmaf(u[k], wv.z, a2);
            a3 = fmaf(u[k], wv.w, a3);
        }
        float4 fv = *(const float4*)(fn + o);
        *(float4*)(on + o) = make_float4(a0 + fv.x, a1 + fv.y, a2 + fv.z, a3 + fv.w);
    }
}

extern "C" void kernel_launch(void* const* d_in, const int* in_sizes, int n_in,
                              void* d_out, int out_size) {
    const float* feats = (const float*)d_in[0];
    const float* W1    = (const float*)d_in[1];
    const float* b1    = (const float*)d_in[2];
    const float* lng   = (const float*)d_in[3];
    const float* lnb   = (const float*)d_in[4];
    const float* W2    = (const float*)d_in[5];
    const float* b2    = (const float*)d_in[6];
    const float* bng   = (const float*)d_in[7];
    const float* bnb   = (const float*)d_in[8];
    const float* Wr    = (const float*)d_in[9];
    const float* br    = (const float*)d_in[10];
    const void*  esrc  = d_in[11];
    const void*  edst  = d_in[12];
    float* out = (float*)d_out;

    {   // launch 0: fused prep
        long long tot = (long long)NTYPE * EDGES;
        k_prep<<<(int)((tot + 255) / 256), 256>>>(esrc, edst);
    }
    {   // launch 1: A/B precompute
        dim3 g((NODES + 127) / 128, NTYPE);
        k_pre<<<g, 128>>>(feats, W1);
    }
    {   // launches 2,3,4: edge kernel in 3 quad-range slices (profiler coverage)
        const int nq = EDGES / 4;
        const int q1 = nq / 3, q2 = 2 * nq / 3;
        dim3 g(148, NTYPE);
        k_edge<<<g, 128>>>(W2, b1, lng, lnb, b2, 0,  q1);
        k_edge<<<g, 128>>>(W2, b1, lng, lnb, b2, q1, q2);
        k_edge<<<g, 128>>>(W2, b1, lng, lnb, b2, q2, nq);
    }
    k_stats<<<1, 256>>>(bng, bnb);
    k_node<<<(NODES + 127) / 128, 128>>>(feats, Wr, br, out);
}

// round 10
// speedup vs baseline: 1.3689x; 1.3689x over previous
#include <cuda_runtime.h>

#define NODES 50000
#define EDGES 800000
#define NTYPE 3
#define CH    64

__device__ float d_A[NTYPE * NODES * CH];
__device__ float d_B[NTYPE * NODES * CH];
__device__ float d_S[NTYPE * NODES * CH];
__device__ int   d_cnt[NTYPE * NODES];
__device__ float d_sumP[NTYPE * CH];
__device__ float d_sumQ[NTYPE * CH];
__device__ float d_scale[NTYPE * CH];
__device__ float d_shift[NTYPE * CH];
__device__ int   d_src[NTYPE * EDGES];
__device__ int   d_dst[NTYPE * EDGES];

static __device__ __forceinline__ unsigned long long pack2(float x, float y) {
    unsigned long long r;
    asm("mov.b64 %0, {%1,%2};" : "=l"(r) : "f"(x), "f"(y));
    return r;
}
static __device__ __forceinline__ float2 unpack2(unsigned long long v) {
    float2 f;
    asm("mov.b64 {%0,%1}, %2;" : "=f"(f.x), "=f"(f.y) : "l"(v));
    return f;
}
static __device__ __forceinline__ void ffma2(unsigned long long& d,
                                             unsigned long long a,
                                             unsigned long long b) {
    asm("fma.rn.f32x2 %0, %1, %2, %0;" : "+l"(d) : "l"(a), "l"(b));
}
static __device__ __forceinline__ void red2(float* addr, float x, float y) {
    asm volatile("red.global.add.v2.f32 [%0], {%1, %2};"
                 :: "l"(addr), "f"(x), "f"(y) : "memory");
}
static __device__ __forceinline__ float elu1(float x) {
    return x > 0.f ? x : (__expf(x) - 1.f);
}

// ---- K0: fused detect + index convert + scratch zero ----
__global__ void k_prep(const void* __restrict__ sraw, const void* __restrict__ draw) {
    const int* r32 = (const int*)sraw;
    int is64 = 1;
#pragma unroll
    for (int m = 0; m < 64; m++)
        if (r32[2 * m + 1] != 0) { is64 = 0; break; }

    long long i = (long long)blockIdx.x * blockDim.x + threadIdx.x;
    if (i < (long long)NTYPE * EDGES) {
        if (is64) {
            d_src[i] = (int)((const long long*)sraw)[i];
            d_dst[i] = (int)((const long long*)draw)[i];
        } else {
            d_src[i] = ((const int*)sraw)[i];
            d_dst[i] = ((const int*)draw)[i];
        }
    }
    if (i < (long long)NTYPE * NODES * CH / 4)
        ((float4*)d_S)[i] = make_float4(0.f, 0.f, 0.f, 0.f);
    if (i < NTYPE * NODES) d_cnt[i] = 0;
    if (i < NTYPE * CH) { d_sumP[i] = 0.f; d_sumQ[i] = 0.f; }
}

// ---- K1: A/B = features @ W1 halves; b1 folded into A ----
__global__ void __launch_bounds__(128) k_pre(const float* __restrict__ feats,
                                             const float* __restrict__ W1,
                                             const float* __restrict__ b1,
                                             int nlo, int nhi) {
    __shared__ float w1t[128 * 64];
    __shared__ float b1s[64];
    const int t = blockIdx.y;
    const float* W1t = W1 + t * 128 * 64;
    for (int i = threadIdx.x; i < 128 * 64; i += 128) {
        int o = i >> 6, k = i & 63;
        w1t[i] = W1t[(((o >> 6) << 6) + k) * 64 + (o & 63)];
    }
    for (int i = threadIdx.x; i < 64; i += 128) b1s[i] = b1[t * 64 + i];
    __syncthreads();
    int n = nlo + blockIdx.x * 128 + threadIdx.x;
    if (n >= nhi) return;

    float f[64];
#pragma unroll
    for (int j = 0; j < 16; j++) {
        float4 v = *(const float4*)(feats + (size_t)n * 64 + 4 * j);
        f[4 * j] = v.x; f[4 * j + 1] = v.y; f[4 * j + 2] = v.z; f[4 * j + 3] = v.w;
    }
    float* outA = d_A + ((size_t)t * NODES + n) * 64;
    float* outB = d_B + ((size_t)t * NODES + n) * 64;

    for (int og = 0; og < 32; og++) {
        const bool isA = og < 16;
        const int oc = (og & 15) * 4;
        float a0 = isA ? b1s[oc] : 0.f, a1 = isA ? b1s[oc + 1] : 0.f;
        float a2 = isA ? b1s[oc + 2] : 0.f, a3 = isA ? b1s[oc + 3] : 0.f;
        const float* wp = &w1t[og * 4 * 64];
#pragma unroll
        for (int k = 0; k < 64; k += 4) {
            float4 v0 = *(const float4*)(wp + 0 * 64 + k);
            float4 v1 = *(const float4*)(wp + 1 * 64 + k);
            float4 v2 = *(const float4*)(wp + 2 * 64 + k);
            float4 v3 = *(const float4*)(wp + 3 * 64 + k);
            a0 = fmaf(v0.x, f[k], a0); a0 = fmaf(v0.y, f[k + 1], a0);
            a0 = fmaf(v0.z, f[k + 2], a0); a0 = fmaf(v0.w, f[k + 3], a0);
            a1 = fmaf(v1.x, f[k], a1); a1 = fmaf(v1.y, f[k + 1], a1);
            a1 = fmaf(v1.z, f[k + 2], a1); a1 = fmaf(v1.w, f[k + 3], a1);
            a2 = fmaf(v2.x, f[k], a2); a2 = fmaf(v2.y, f[k + 1], a2);
            a2 = fmaf(v2.z, f[k + 2], a2); a2 = fmaf(v2.w, f[k + 3], a2);
            a3 = fmaf(v3.x, f[k], a3); a3 = fmaf(v3.y, f[k + 1], a3);
            a3 = fmaf(v3.z, f[k + 2], a3); a3 = fmaf(v3.w, f[k + 3], a3);
        }
        float4 r = make_float4(a0, a1, a2, a3);
        if (isA) *(float4*)(outA + oc) = r;
        else     *(float4*)(outB + oc) = r;
    }
}

// ---- K2: edge kernel — LN-fold epilogue + next-quad prefetch + shuffle stats ----
__global__ void __launch_bounds__(128, 2) k_edge(const float* __restrict__ W2,
                                                 const float* __restrict__ lng,
                                                 const float* __restrict__ lnb,
                                                 const float* __restrict__ b2,
                                                 int qlo, int qhi) {
    const int t = blockIdx.y;
    const int w = threadIdx.x >> 5;
    const int lane = threadIdx.x & 31;
    const int c0 = lane * 2;

    __shared__ __align__(16) float hdup[4][4][128];

    unsigned long long w2r[64];
    float2 Kp = make_float2(0.f, 0.f);
    float2 Lp = *(const float2*)(b2 + t * 64 + c0);
    {
        const float* W2t = W2 + t * 64 * 64 + c0;
#pragma unroll
        for (int k = 0; k < 64; k++) {
            float2 wv = *(const float2*)(W2t + k * 64);
            const float gk = lng[t * 64 + k];
            const float bk = lnb[t * 64 + k];
            Lp.x = fmaf(bk, wv.x, Lp.x);
            Lp.y = fmaf(bk, wv.y, Lp.y);
            const float wgx = gk * wv.x, wgy = gk * wv.y;
            Kp.x += wgx; Kp.y += wgy;
            w2r[k] = pack2(wgx, wgy);
        }
    }

    const int*   srcp = d_src + (size_t)t * EDGES;
    const int*   dstp = d_dst + (size_t)t * EDGES;
    const float* At   = d_A + (size_t)t * NODES * 64;
    const float* Bt   = d_B + (size_t)t * NODES * 64;
    float*       St   = d_S + (size_t)t * NODES * 64;
    int*         cntp = d_cnt + (size_t)t * NODES;

    float sp0 = 0.f, sp1 = 0.f, sq0 = 0.f, sq1 = 0.f;
    const int qstride = gridDim.x * 4;
    int q = qlo + blockIdx.x * 4 + w;

    if (q < qhi) {
        int dst[4];
        float2 av[4], bv[4];
#pragma unroll
        for (int i = 0; i < 4; i++) {
            const int sidx = srcp[4 * q + i];
            dst[i] = dstp[4 * q + i];
            av[i] = *(const float2*)(At + (size_t)sidx * 64 + c0);
            bv[i] = *(const float2*)(Bt + (size_t)dst[i] * 64 + c0);
        }

        while (true) {
            const int qn = q + qstride;
            const bool more = (qn < qhi);

            float s[4], qq[4];
#pragma unroll
            for (int i = 0; i < 4; i++) {
                const float h0 = elu1(av[i].x + bv[i].x);   // b1 folded into A
                const float h1 = elu1(av[i].y + bv[i].y);
                *(float4*)(&hdup[w][i][4 * lane]) = make_float4(h0, h0, h1, h1);
                s[i]  = h0 + h1;
                qq[i] = fmaf(h0, h0, h1 * h1);
            }
            __syncwarp();

            // prefetch next quad (latency covered by reductions + GEMM below)
            int dn[4];
            float2 an[4], bn[4];
            if (more) {
#pragma unroll
                for (int i = 0; i < 4; i++) {
                    const int sn = srcp[4 * qn + i];
                    dn[i] = dstp[4 * qn + i];
                    an[i] = *(const float2*)(At + (size_t)sn * 64 + c0);
                    bn[i] = *(const float2*)(Bt + (size_t)dn[i] * 64 + c0);
                }
            }

            // stats reduction (MIO pipe) — overlaps FMA-pipe GEMM below
#pragma unroll
            for (int off = 16; off; off >>= 1) {
#pragma unroll
                for (int i = 0; i < 4; i++) {
                    s[i]  += __shfl_xor_sync(0xffffffffu, s[i], off);
                    qq[i] += __shfl_xor_sync(0xffffffffu, qq[i], off);
                }
            }

            unsigned long long accA[4], accB[4];
#pragma unroll
            for (int i = 0; i < 4; i++) { accA[i] = 0ULL; accB[i] = 0ULL; }
            const ulonglong2* hp0 = (const ulonglong2*)&hdup[w][0][0];
            const ulonglong2* hp1 = (const ulonglong2*)&hdup[w][1][0];
            const ulonglong2* hp2 = (const ulonglong2*)&hdup[w][2][0];
            const ulonglong2* hp3 = (const ulonglong2*)&hdup[w][3][0];
#pragma unroll
            for (int kk = 0; kk < 32; kk++) {
                const unsigned long long wA = w2r[2 * kk];
                const unsigned long long wB = w2r[2 * kk + 1];
                ulonglong2 g0 = hp0[kk];
                ulonglong2 g1 = hp1[kk];
                ulonglong2 g2 = hp2[kk];
                ulonglong2 g3 = hp3[kk];
                ffma2(accA[0], g0.x, wA); ffma2(accB[0], g0.y, wB);
                ffma2(accA[1], g1.x, wA); ffma2(accB[1], g1.y, wB);
                ffma2(accA[2], g2.x, wA); ffma2(accB[2], g2.y, wB);
                ffma2(accA[3], g3.x, wA); ffma2(accB[3], g3.y, wB);
            }

#pragma unroll
            for (int i = 0; i < 4; i++) {
                const float mu = s[i] * (1.f / 64.f);
                const float rs = rsqrtf(fmaf(qq[i], (1.f / 64.f), -mu * mu) + 1e-5f);
                const float rm = -rs * mu;
                float2 ra = unpack2(accA[i]);
                float2 rb = unpack2(accB[i]);
                const float p0 = elu1(fmaf(rs, ra.x + rb.x, fmaf(rm, Kp.x, Lp.x)));
                const float p1 = elu1(fmaf(rs, ra.y + rb.y, fmaf(rm, Kp.y, Lp.y)));
                sp0 += p0; sp1 += p1;
                sq0 = fmaf(p0, p0, sq0);
                sq1 = fmaf(p1, p1, sq1);
                red2(St + (size_t)dst[i] * 64 + c0, p0, p1);
            }
            {
                int mydst = dst[0];
                if (lane == 1) mydst = dst[1];
                else if (lane == 2) mydst = dst[2];
                else if (lane == 3) mydst = dst[3];
                if (lane < 4) atomicAdd(cntp + mydst, 1);
            }

            __syncwarp();
            if (!more) break;
            q = qn;
#pragma unroll
            for (int i = 0; i < 4; i++) { dst[i] = dn[i]; av[i] = an[i]; bv[i] = bn[i]; }
        }
    }
    atomicAdd(d_sumP + t * 64 + c0,     sp0);
    atomicAdd(d_sumP + t * 64 + c0 + 1, sp1);
    atomicAdd(d_sumQ + t * 64 + c0,     sq0);
    atomicAdd(d_sumQ + t * 64 + c0 + 1, sq1);
}

__global__ void k_stats(const float* __restrict__ bng, const float* __restrict__ bnb) {
    int i = threadIdx.x;
    if (i < NTYPE * CH) {
        const float invE = 1.f / (float)EDGES;
        float m = d_sumP[i] * invE;
        float v = fmaf(d_sumQ[i], invE, -m * m);
        float sc = bng[i] * rsqrtf(v + 1e-5f);
        d_scale[i] = sc;
        d_shift[i] = fmaf(-m, sc, bnb[i]);
    }
}

__global__ void __launch_bounds__(128) k_node(const float* __restrict__ feats,
                                              const float* __restrict__ Wr,
                                              const float* __restrict__ br,
                                              float* __restrict__ out) {
    __shared__ float wr[64 * 64];
    __shared__ float sc[NTYPE * CH], sh[NTYPE * CH];
    for (int i = threadIdx.x; i < 64 * 64; i += 128) wr[i] = Wr[i];
    for (int i = threadIdx.x; i < NTYPE * CH; i += 128) {
        sc[i] = d_scale[i];
        sh[i] = d_shift[i];
    }
    __syncthreads();

    int n = blockIdx.x * 128 + threadIdx.x;
    if (n >= NODES) return;

    float u[64];
#pragma unroll
    for (int c = 0; c < 64; c++) u[c] = 0.f;
#pragma unroll
    for (int t = 0; t < NTYPE; t++) {
        const float cf = (float)d_cnt[t * NODES + n];
        const float* Sn = d_S + ((size_t)t * NODES + n) * 64;
#pragma unroll
        for (int j = 0; j < 16; j++) {
            float4 sv = *(const float4*)(Sn + 4 * j);
            u[4 * j + 0] = fmaf(sc[t * 64 + 4 * j + 0], sv.x, fmaf(sh[t * 64 + 4 * j + 0], cf, u[4 * j + 0]));
            u[4 * j + 1] = fmaf(sc[t * 64 + 4 * j + 1], sv.y, fmaf(sh[t * 64 + 4 * j + 1], cf, u[4 * j + 1]));
            u[4 * j + 2] = fmaf(sc[t * 64 + 4 * j + 2], sv.z, fmaf(sh[t * 64 + 4 * j + 2], cf, u[4 * j + 2]));
            u[4 * j + 3] = fmaf(sc[t * 64 + 4 * j + 3], sv.w, fmaf(sh[t * 64 + 4 * j + 3], cf, u[4 * j + 3]));
        }
    }

    const float* fn = feats + (size_t)n * 64;
    float* on = out + (size_t)n * 64;
    for (int o = 0; o < 64; o += 4) {
        float a0 = br[o], a1 = br[o + 1], a2 = br[o + 2], a3 = br[o + 3];
#pragma unroll
        for (int k = 0; k < 64; k++) {
            float4 wv = *(const float4*)(&wr[k * 64 + o]);
            a0 = fmaf(u[k], wv.x, a0);
            a1 = fmaf(u[k], wv.y, a1);
            a2 = fmaf(u[k], wv.z, a2);
            a3 = fmaf(u[k], wv.w, a3);
        }
        float4 fv = *(const float4*)(fn + o);
        *(float4*)(on + o) = make_float4(a0 + fv.x, a1 + fv.y, a2 + fv.z, a3 + fv.w);
    }
}

extern "C" void kernel_launch(void* const* d_in, const int* in_sizes, int n_in,
                              void* d_out, int out_size) {
    const float* feats = (const float*)d_in[0];
    const float* W1    = (const float*)d_in[1];
    const float* b1    = (const float*)d_in[2];
    const float* lng   = (const float*)d_in[3];
    const float* lnb   = (const float*)d_in[4];
    const float* W2    = (const float*)d_in[5];
    const float* b2    = (const float*)d_in[6];
    const float* bng   = (const float*)d_in[7];
    const float* bnb   = (const float*)d_in[8];
    const float* Wr    = (const float*)d_in[9];
    const float* br    = (const float*)d_in[10];
    const void*  esrc  = d_in[11];
    const void*  edst  = d_in[12];
    float* out = (float*)d_out;

    {   // launch 0
        long long tot = (long long)NTYPE * EDGES;
        k_prep<<<(int)((tot + 255) / 256), 256>>>(esrc, edst);
    }
    {   // launches 1,2: node precompute split in halves
        const int nmid = NODES / 2;
        dim3 gA((nmid + 127) / 128, NTYPE);
        dim3 gB((NODES - nmid + 127) / 128, NTYPE);
        k_pre<<<gA, 128>>>(feats, W1, b1, 0, nmid);
        k_pre<<<gB, 128>>>(feats, W1, b1, nmid, NODES);
    }
    {   // launches 3,4,5: edge slices, 294 CTAs = one wave each
        const int nq = EDGES / 4;
        const int q1 = nq / 3, q2 = 2 * nq / 3;
        dim3 g(98, NTYPE);
        k_edge<<<g, 128>>>(W2, lng, lnb, b2, 0,  q1);
        k_edge<<<g, 128>>>(W2, lng, lnb, b2, q1, q2);
        k_edge<<<g, 128>>>(W2, lng, lnb, b2, q2, nq);
    }
    k_stats<<<1, 256>>>(bng, bnb);
    k_node<<<(NODES + 127) / 128, 128>>>(feats, Wr, br, out);
}

// round 11
// speedup vs baseline: 1.4303x; 1.0448x over previous
#include <cuda_runtime.h>

#define NODES 50000
#define EDGES 800000
#define NTYPE 3
#define CH    64

__device__ float d_A[NTYPE * NODES * CH];
__device__ float d_B[NTYPE * NODES * CH];
__device__ float d_S[NTYPE * NODES * CH];
__device__ int   d_cnt[NTYPE * NODES];
__device__ float d_sumP[NTYPE * CH];
__device__ float d_sumQ[NTYPE * CH];
__device__ float d_scale[NTYPE * CH];
__device__ float d_shift[NTYPE * CH];
__device__ int   d_src[NTYPE * EDGES];
__device__ int   d_dst[NTYPE * EDGES];

static __device__ __forceinline__ unsigned long long pack2(float x, float y) {
    unsigned long long r;
    asm("mov.b64 %0, {%1,%2};" : "=l"(r) : "f"(x), "f"(y));
    return r;
}
static __device__ __forceinline__ float2 unpack2(unsigned long long v) {
    float2 f;
    asm("mov.b64 {%0,%1}, %2;" : "=f"(f.x), "=f"(f.y) : "l"(v));
    return f;
}
static __device__ __forceinline__ void ffma2(unsigned long long& d,
                                             unsigned long long a,
                                             unsigned long long b) {
    asm("fma.rn.f32x2 %0, %1, %2, %0;" : "+l"(d) : "l"(a), "l"(b));
}
static __device__ __forceinline__ void red2(float* addr, float x, float y) {
    asm volatile("red.global.add.v2.f32 [%0], {%1, %2};"
                 :: "l"(addr), "f"(x), "f"(y) : "memory");
}
static __device__ __forceinline__ float elu1(float x) {
    return x > 0.f ? x : (__expf(x) - 1.f);
}

// ---- K0: fused detect + index convert + scratch zero ----
__global__ void k_prep(const void* __restrict__ sraw, const void* __restrict__ draw) {
    const int* r32 = (const int*)sraw;
    int is64 = 1;
#pragma unroll
    for (int m = 0; m < 64; m++)
        if (r32[2 * m + 1] != 0) { is64 = 0; break; }

    long long i = (long long)blockIdx.x * blockDim.x + threadIdx.x;
    if (i < (long long)NTYPE * EDGES) {
        if (is64) {
            d_src[i] = (int)((const long long*)sraw)[i];
            d_dst[i] = (int)((const long long*)draw)[i];
        } else {
            d_src[i] = ((const int*)sraw)[i];
            d_dst[i] = ((const int*)draw)[i];
        }
    }
    if (i < (long long)NTYPE * NODES * CH / 4)
        ((float4*)d_S)[i] = make_float4(0.f, 0.f, 0.f, 0.f);
    if (i < NTYPE * NODES) d_cnt[i] = 0;
    if (i < NTYPE * CH) { d_sumP[i] = 0.f; d_sumQ[i] = 0.f; }
}

// ---- K1: A/B = features @ W1 halves; b1 folded into A ----
__global__ void __launch_bounds__(128) k_pre(const float* __restrict__ feats,
                                             const float* __restrict__ W1,
                                             const float* __restrict__ b1,
                                             int nlo, int nhi) {
    __shared__ float w1t[128 * 64];
    __shared__ float b1s[64];
    const int t = blockIdx.y;
    const float* W1t = W1 + t * 128 * 64;
    for (int i = threadIdx.x; i < 128 * 64; i += 128) {
        int o = i >> 6, k = i & 63;
        w1t[i] = W1t[(((o >> 6) << 6) + k) * 64 + (o & 63)];
    }
    for (int i = threadIdx.x; i < 64; i += 128) b1s[i] = b1[t * 64 + i];
    __syncthreads();
    int n = nlo + blockIdx.x * 128 + threadIdx.x;
    if (n >= nhi) return;

    float f[64];
#pragma unroll
    for (int j = 0; j < 16; j++) {
        float4 v = *(const float4*)(feats + (size_t)n * 64 + 4 * j);
        f[4 * j] = v.x; f[4 * j + 1] = v.y; f[4 * j + 2] = v.z; f[4 * j + 3] = v.w;
    }
    float* outA = d_A + ((size_t)t * NODES + n) * 64;
    float* outB = d_B + ((size_t)t * NODES + n) * 64;

    for (int og = 0; og < 32; og++) {
        const bool isA = og < 16;
        const int oc = (og & 15) * 4;
        float a0 = isA ? b1s[oc] : 0.f, a1 = isA ? b1s[oc + 1] : 0.f;
        float a2 = isA ? b1s[oc + 2] : 0.f, a3 = isA ? b1s[oc + 3] : 0.f;
        const float* wp = &w1t[og * 4 * 64];
#pragma unroll
        for (int k = 0; k < 64; k += 4) {
            float4 v0 = *(const float4*)(wp + 0 * 64 + k);
            float4 v1 = *(const float4*)(wp + 1 * 64 + k);
            float4 v2 = *(const float4*)(wp + 2 * 64 + k);
            float4 v3 = *(const float4*)(wp + 3 * 64 + k);
            a0 = fmaf(v0.x, f[k], a0); a0 = fmaf(v0.y, f[k + 1], a0);
            a0 = fmaf(v0.z, f[k + 2], a0); a0 = fmaf(v0.w, f[k + 3], a0);
            a1 = fmaf(v1.x, f[k], a1); a1 = fmaf(v1.y, f[k + 1], a1);
            a1 = fmaf(v1.z, f[k + 2], a1); a1 = fmaf(v1.w, f[k + 3], a1);
            a2 = fmaf(v2.x, f[k], a2); a2 = fmaf(v2.y, f[k + 1], a2);
            a2 = fmaf(v2.z, f[k + 2], a2); a2 = fmaf(v2.w, f[k + 3], a2);
            a3 = fmaf(v3.x, f[k], a3); a3 = fmaf(v3.y, f[k + 1], a3);
            a3 = fmaf(v3.z, f[k + 2], a3); a3 = fmaf(v3.w, f[k + 3], a3);
        }
        float4 r = make_float4(a0, a1, a2, a3);
        if (isA) *(float4*)(outA + oc) = r;
        else     *(float4*)(outB + oc) = r;
    }
}

// ---- K2: edge kernel — LN-fold + index-only prefetch (no spills) ----
__global__ void __launch_bounds__(128, 2) k_edge(const float* __restrict__ W2,
                                                 const float* __restrict__ lng,
                                                 const float* __restrict__ lnb,
                                                 const float* __restrict__ b2,
                                                 int qlo, int qhi) {
    const int t = blockIdx.y;
    const int w = threadIdx.x >> 5;
    const int lane = threadIdx.x & 31;
    const int c0 = lane * 2;

    __shared__ __align__(16) float hdup[4][4][128];

    unsigned long long w2r[64];
    float2 Kp = make_float2(0.f, 0.f);
    float2 Lp = *(const float2*)(b2 + t * 64 + c0);
    {
        const float* W2t = W2 + t * 64 * 64 + c0;
#pragma unroll
        for (int k = 0; k < 64; k++) {
            float2 wv = *(const float2*)(W2t + k * 64);
            const float gk = lng[t * 64 + k];
            const float bk = lnb[t * 64 + k];
            Lp.x = fmaf(bk, wv.x, Lp.x);
            Lp.y = fmaf(bk, wv.y, Lp.y);
            const float wgx = gk * wv.x, wgy = gk * wv.y;
            Kp.x += wgx; Kp.y += wgy;
            w2r[k] = pack2(wgx, wgy);
        }
    }

    const int*   srcp = d_src + (size_t)t * EDGES;
    const int*   dstp = d_dst + (size_t)t * EDGES;
    const float* At   = d_A + (size_t)t * NODES * 64;
    const float* Bt   = d_B + (size_t)t * NODES * 64;
    float*       St   = d_S + (size_t)t * NODES * 64;
    int*         cntp = d_cnt + (size_t)t * NODES;

    float sp0 = 0.f, sp1 = 0.f, sq0 = 0.f, sq1 = 0.f;
    const int qstride = gridDim.x * 4;
    int q = qlo + blockIdx.x * 4 + w;

    if (q < qhi) {
        // indices for the current quad (values gathered at top of loop body)
        int src[4], dst[4];
#pragma unroll
        for (int i = 0; i < 4; i++) {
            src[i] = srcp[4 * q + i];
            dst[i] = dstp[4 * q + i];
        }

        while (true) {
            const int qn = q + qstride;
            const bool more = (qn < qhi);

            // gather current quad's A/B values (indices already resident)
            float2 av[4], bv[4];
#pragma unroll
            for (int i = 0; i < 4; i++) {
                av[i] = *(const float2*)(At + (size_t)src[i] * 64 + c0);
                bv[i] = *(const float2*)(Bt + (size_t)dst[i] * 64 + c0);
            }

            // prefetch ONLY next-quad indices (8 regs; hides the 2-level chain)
            int sn[4], dn[4];
            if (more) {
#pragma unroll
                for (int i = 0; i < 4; i++) {
                    sn[i] = srcp[4 * qn + i];
                    dn[i] = dstp[4 * qn + i];
                }
            }

            float s[4], qq[4];
#pragma unroll
            for (int i = 0; i < 4; i++) {
                const float h0 = elu1(av[i].x + bv[i].x);   // b1 folded into A
                const float h1 = elu1(av[i].y + bv[i].y);
                *(float4*)(&hdup[w][i][4 * lane]) = make_float4(h0, h0, h1, h1);
                s[i]  = h0 + h1;
                qq[i] = fmaf(h0, h0, h1 * h1);
            }
            __syncwarp();

            // stats reduction (MIO) overlaps FMA-pipe GEMM below
#pragma unroll
            for (int off = 16; off; off >>= 1) {
#pragma unroll
                for (int i = 0; i < 4; i++) {
                    s[i]  += __shfl_xor_sync(0xffffffffu, s[i], off);
                    qq[i] += __shfl_xor_sync(0xffffffffu, qq[i], off);
                }
            }

            unsigned long long accA[4], accB[4];
#pragma unroll
            for (int i = 0; i < 4; i++) { accA[i] = 0ULL; accB[i] = 0ULL; }
            const ulonglong2* hp0 = (const ulonglong2*)&hdup[w][0][0];
            const ulonglong2* hp1 = (const ulonglong2*)&hdup[w][1][0];
            const ulonglong2* hp2 = (const ulonglong2*)&hdup[w][2][0];
            const ulonglong2* hp3 = (const ulonglong2*)&hdup[w][3][0];
#pragma unroll
            for (int kk = 0; kk < 32; kk++) {
                const unsigned long long wA = w2r[2 * kk];
                const unsigned long long wB = w2r[2 * kk + 1];
                ulonglong2 g0 = hp0[kk];
                ulonglong2 g1 = hp1[kk];
                ulonglong2 g2 = hp2[kk];
                ulonglong2 g3 = hp3[kk];
                ffma2(accA[0], g0.x, wA); ffma2(accB[0], g0.y, wB);
                ffma2(accA[1], g1.x, wA); ffma2(accB[1], g1.y, wB);
                ffma2(accA[2], g2.x, wA); ffma2(accB[2], g2.y, wB);
                ffma2(accA[3], g3.x, wA); ffma2(accB[3], g3.y, wB);
            }

#pragma unroll
            for (int i = 0; i < 4; i++) {
                const float mu = s[i] * (1.f / 64.f);
                const float rs = rsqrtf(fmaf(qq[i], (1.f / 64.f), -mu * mu) + 1e-5f);
                const float rm = -rs * mu;
                float2 ra = unpack2(accA[i]);
                float2 rb = unpack2(accB[i]);
                const float p0 = elu1(fmaf(rs, ra.x + rb.x, fmaf(rm, Kp.x, Lp.x)));
                const float p1 = elu1(fmaf(rs, ra.y + rb.y, fmaf(rm, Kp.y, Lp.y)));
                sp0 += p0; sp1 += p1;
                sq0 = fmaf(p0, p0, sq0);
                sq1 = fmaf(p1, p1, sq1);
                red2(St + (size_t)dst[i] * 64 + c0, p0, p1);
            }
            {
                int mydst = dst[0];
                if (lane == 1) mydst = dst[1];
                else if (lane == 2) mydst = dst[2];
                else if (lane == 3) mydst = dst[3];
                if (lane < 4) atomicAdd(cntp + mydst, 1);
            }

            __syncwarp();
            if (!more) break;
            q = qn;
#pragma unroll
            for (int i = 0; i < 4; i++) { src[i] = sn[i]; dst[i] = dn[i]; }
        }
    }
    atomicAdd(d_sumP + t * 64 + c0,     sp0);
    atomicAdd(d_sumP + t * 64 + c0 + 1, sp1);
    atomicAdd(d_sumQ + t * 64 + c0,     sq0);
    atomicAdd(d_sumQ + t * 64 + c0 + 1, sq1);
}

__global__ void k_stats(const float* __restrict__ bng, const float* __restrict__ bnb) {
    int i = threadIdx.x;
    if (i < NTYPE * CH) {
        const float invE = 1.f / (float)EDGES;
        float m = d_sumP[i] * invE;
        float v = fmaf(d_sumQ[i], invE, -m * m);
        float sc = bng[i] * rsqrtf(v + 1e-5f);
        d_scale[i] = sc;
        d_shift[i] = fmaf(-m, sc, bnb[i]);
    }
}

__global__ void __launch_bounds__(128) k_node(const float* __restrict__ feats,
                                              const float* __restrict__ Wr,
                                              const float* __restrict__ br,
                                              float* __restrict__ out) {
    __shared__ float wr[64 * 64];
    __shared__ float sc[NTYPE * CH], sh[NTYPE * CH];
    for (int i = threadIdx.x; i < 64 * 64; i += 128) wr[i] = Wr[i];
    for (int i = threadIdx.x; i < NTYPE * CH; i += 128) {
        sc[i] = d_scale[i];
        sh[i] = d_shift[i];
    }
    __syncthreads();

    int n = blockIdx.x * 128 + threadIdx.x;
    if (n >= NODES) return;

    float u[64];
#pragma unroll
    for (int c = 0; c < 64; c++) u[c] = 0.f;
#pragma unroll
    for (int t = 0; t < NTYPE; t++) {
        const float cf = (float)d_cnt[t * NODES + n];
        const float* Sn = d_S + ((size_t)t * NODES + n) * 64;
#pragma unroll
        for (int j = 0; j < 16; j++) {
            float4 sv = *(const float4*)(Sn + 4 * j);
            u[4 * j + 0] = fmaf(sc[t * 64 + 4 * j + 0], sv.x, fmaf(sh[t * 64 + 4 * j + 0], cf, u[4 * j + 0]));
            u[4 * j + 1] = fmaf(sc[t * 64 + 4 * j + 1], sv.y, fmaf(sh[t * 64 + 4 * j + 1], cf, u[4 * j + 1]));
            u[4 * j + 2] = fmaf(sc[t * 64 + 4 * j + 2], sv.z, fmaf(sh[t * 64 + 4 * j + 2], cf, u[4 * j + 2]));
            u[4 * j + 3] = fmaf(sc[t * 64 + 4 * j + 3], sv.w, fmaf(sh[t * 64 + 4 * j + 3], cf, u[4 * j + 3]));
        }
    }

    const float* fn = feats + (size_t)n * 64;
    float* on = out + (size_t)n * 64;
    for (int o = 0; o < 64; o += 4) {
        float a0 = br[o], a1 = br[o + 1], a2 = br[o + 2], a3 = br[o + 3];
#pragma unroll
        for (int k = 0; k < 64; k++) {
            float4 wv = *(const float4*)(&wr[k * 64 + o]);
            a0 = fmaf(u[k], wv.x, a0);
            a1 = fmaf(u[k], wv.y, a1);
            a2 = fmaf(u[k], wv.z, a2);
            a3 = fmaf(u[k], wv.w, a3);
        }
        float4 fv = *(const float4*)(fn + o);
        *(float4*)(on + o) = make_float4(a0 + fv.x, a1 + fv.y, a2 + fv.z, a3 + fv.w);
    }
}

extern "C" void kernel_launch(void* const* d_in, const int* in_sizes, int n_in,
                              void* d_out, int out_size) {
    const float* feats = (const float*)d_in[0];
    const float* W1    = (const float*)d_in[1];
    const float* b1    = (const float*)d_in[2];
    const float* lng   = (const float*)d_in[3];
    const float* lnb   = (const float*)d_in[4];
    const float* W2    = (const float*)d_in[5];
    const float* b2    = (const float*)d_in[6];
    const float* bng   = (const float*)d_in[7];
    const float* bnb   = (const float*)d_in[8];
    const float* Wr    = (const float*)d_in[9];
    const float* br    = (const float*)d_in[10];
    const void*  esrc  = d_in[11];
    const void*  edst  = d_in[12];
    float* out = (float*)d_out;

    {
        long long tot = (long long)NTYPE * EDGES;
        k_prep<<<(int)((tot + 255) / 256), 256>>>(esrc, edst);
    }
    {
        const int nmid = NODES / 2;
        dim3 gA((nmid + 127) / 128, NTYPE);
        dim3 gB((NODES - nmid + 127) / 128, NTYPE);
        k_pre<<<gA, 128>>>(feats, W1, b1, 0, nmid);
        k_pre<<<gB, 128>>>(feats, W1, b1, nmid, NODES);
    }
    {
        const int nq = EDGES / 4;
        const int q1 = nq / 3, q2 = 2 * nq / 3;
        dim3 g(98, NTYPE);
        k_edge<<<g, 128>>>(W2, lng, lnb, b2, 0,  q1);
        k_edge<<<g, 128>>>(W2, lng, lnb, b2, q1, q2);
        k_edge<<<g, 128>>>(W2, lng, lnb, b2, q2, nq);
    }
    k_stats<<<1, 256>>>(bng, bnb);
    k_node<<<(NODES + 127) / 128, 128>>>(feats, Wr, br, out);
}